// round 17
// baseline (speedup 1.0000x reference)
#include <cuda_runtime.h>

// LogSpaceSinkhorn: 64 independent 1024x1024 fp32 matrices.
// Multiplicative Sinkhorn: z = 2^(y*scale), w_j = 2^(-v_j) = rcp(sum_i z_ij/S_i)_prev,
// S_i = sum_j z_ij*w_j, u_i = lg2(S_i).
// Register-resident body: each lane keeps its row's z values (t[32]) and its
// column partials (p[32]) in registers; after the shfl row-reduce, p += t/S for
// the lane's own 32 columns. NO smem tile, NO body barriers, no STS/LDS.
// Column sums accumulate via red.global.add.v2 into per-matrix 4KB buffers
// (triple-buffered rotation: read/write/zero, self-sustaining across replays).
// Chunks of 16 matrices stay L2-resident (64MB << 126MB).

#define NN    1024
#define BMAX  64
#define CHUNK 16
#define RPW   4                    // rows per warp
#define CPM   64                   // CTAs per matrix (16 rows per CTA)

static __device__ __align__(16) float g_u[BMAX * NN];
static __device__ __align__(16) float g_w[BMAX * NN];          // final blend
static __device__ __align__(16) float g_B[3][CHUNK * NN];      // rotating P sums

__device__ __forceinline__ float ex2f(float x) {
    float y; asm("ex2.approx.ftz.f32 %0, %1;" : "=f"(y) : "f"(x)); return y;
}
__device__ __forceinline__ float lg2f(float x) {
    float y; asm("lg2.approx.ftz.f32 %0, %1;" : "=f"(y) : "f"(x)); return y;
}
__device__ __forceinline__ float rcpf(float x) {
    float y; asm("rcp.approx.ftz.f32 %0, %1;" : "=f"(y) : "f"(x)); return y;
}
__device__ __forceinline__ void red_add2(float* p, float a, float b) {
    asm volatile("red.global.add.v2.f32 [%0], {%1, %2};"
                 :: "l"(p), "f"(a), "f"(b) : "memory");
}
__device__ __forceinline__ float get_scale(const float* __restrict__ tau) {
    return 1.4426950408889634f / fmaxf(*tau, 0.1f);   // log2(e)/max(tau,0.1)
}

// One pass: head w = rcp(B[br]) into smem; body: warp per 4 rows, lane owns
// columns j = it*128+lane*4, z in regs, S via shfl, p += z/S in regs,
// emit via red.v2 to B[bw]. Zeroes this CTA's slice of B[bz].
__global__ void __launch_bounds__(128, 5) fused_pass(
    const float* __restrict__ a, const float* __restrict__ tau,
    int use_head, int save_u, int mbase, int br, int bw, int bz)
{
    __shared__ float sw[NN];        // 4 KB: w for this matrix

    int cta  = blockIdx.x;          // chunk-local: mi*CPM + rb
    int mi   = cta >> 6;
    int rb   = cta & (CPM - 1);
    int m    = mbase + mi;
    int tid  = threadIdx.x;
    int lane = tid & 31;
    int w    = tid >> 5;

    float scale = get_scale(tau);

    // Zero next-writer slice: grid = nm*64 CTAs, used region nm*1024 floats
    // -> 16 floats per CTA.
    if (tid < 16) g_B[bz][cta * 16 + tid] = 0.f;

    // Head: w_j = rcp(B[br][mi][j]) — previous pass's completed column sums.
    if (use_head) {
#pragma unroll
        for (int k = 0; k < 2; ++k) {
            int i4 = tid + k * 128;
            float4 s4 = reinterpret_cast<const float4*>(g_B[br] + (mi << 10))[i4];
            float4 wv;
            wv.x = rcpf(s4.x); wv.y = rcpf(s4.y);
            wv.z = rcpf(s4.z); wv.w = rcpf(s4.w);
            reinterpret_cast<float4*>(sw)[i4] = wv;
        }
    } else {
#pragma unroll
        for (int k = 0; k < 2; ++k)
            reinterpret_cast<float4*>(sw)[tid + k * 128] =
                make_float4(1.f, 1.f, 1.f, 1.f);
    }
    __syncthreads();                // the ONLY block barrier

    // Body: warp owns rows rb*16 + w*4 .. +3. No further synchronization.
    float p[32];
#pragma unroll
    for (int k = 0; k < 32; ++k) p[k] = 0.f;

    int row0 = rb * 16 + w * RPW;
    const float* __restrict__ abase = a + ((size_t)m << 20) + ((size_t)row0 << 10);

#pragma unroll
    for (int r = 0; r < RPW; ++r) {
        const float* __restrict__ arow = abase + ((size_t)r << 10);
        float t[32];
        float s0 = 0.f, s1 = 0.f, s2 = 0.f, s3 = 0.f;
#pragma unroll
        for (int it = 0; it < 8; ++it) {
            int j = it * 128 + lane * 4;
            float4 av = *reinterpret_cast<const float4*>(arow + j);
            float4 wv = *reinterpret_cast<const float4*>(sw + j);
            float z0 = ex2f(av.x * scale);
            float z1 = ex2f(av.y * scale);
            float z2 = ex2f(av.z * scale);
            float z3 = ex2f(av.w * scale);
            t[it * 4 + 0] = z0; t[it * 4 + 1] = z1;
            t[it * 4 + 2] = z2; t[it * 4 + 3] = z3;
            s0 = fmaf(z0, wv.x, s0); s1 = fmaf(z1, wv.y, s1);
            s2 = fmaf(z2, wv.z, s2); s3 = fmaf(z3, wv.w, s3);
        }
        float s = (s0 + s1) + (s2 + s3);
#pragma unroll
        for (int o = 16; o; o >>= 1) s += __shfl_xor_sync(0xffffffffu, s, o);
        if (save_u && lane == 0) g_u[(m << 10) + row0 + r] = lg2f(s);
        float rS = rcpf(s);
#pragma unroll
        for (int k = 0; k < 32; ++k) p[k] = fmaf(t[k], rS, p[k]);
    }

    // Emit this warp's column partials straight from registers.
    float* __restrict__ dst = g_B[bw] + (mi << 10);
#pragma unroll
    for (int it = 0; it < 8; ++it) {
        int j = it * 128 + lane * 4;
        red_add2(dst + j,     p[it * 4 + 0], p[it * 4 + 1]);
        red_add2(dst + j + 2, p[it * 4 + 2], p[it * 4 + 3]);
    }
}

// Final blend: g_w = 0.5*(v5 + v6), v5 = lg2(B[1]) (sum P4), v6 = lg2(B[2]) (sum P5).
__global__ void __launch_bounds__(256) vsum_final(int mbase)
{
    int mi = blockIdx.x;
    int m  = mbase + mi;
    int t  = threadIdx.x;

    float4 s5 = reinterpret_cast<const float4*>(g_B[1] + (mi << 10))[t];
    float4 s6 = reinterpret_cast<const float4*>(g_B[2] + (mi << 10))[t];
    float4 wb;
    wb.x = 0.5f * (lg2f(s5.x) + lg2f(s6.x));
    wb.y = 0.5f * (lg2f(s5.y) + lg2f(s6.y));
    wb.z = 0.5f * (lg2f(s5.z) + lg2f(s6.z));
    wb.w = 0.5f * (lg2f(s5.w) + lg2f(s6.w));
    reinterpret_cast<float4*>(g_w + (m << 10))[t] = wb;
}

// out_ij = 2^(y*scale - u6_i - wblend_j).
__global__ void __launch_bounds__(256) finalize_k(
    const float* __restrict__ a, const float* __restrict__ tau,
    float* __restrict__ out, int mbase)
{
    size_t e = ((size_t)(blockIdx.x * blockDim.x + threadIdx.x) << 2)
             + ((size_t)mbase << 20);
    int m   = (int)(e >> 20);
    int row = (int)(e >> 10) & 1023;
    int j   = (int)(e & 1023);

    float scale = get_scale(tau);
    float uv = g_u[(m << 10) + row];
    float4 wv = *reinterpret_cast<const float4*>(&g_w[(m << 10) + j]);
    float4 av = *reinterpret_cast<const float4*>(a + e);

    float4 r;
    r.x = ex2f(fmaf(av.x, scale, -(uv + wv.x)));
    r.y = ex2f(fmaf(av.y, scale, -(uv + wv.y)));
    r.z = ex2f(fmaf(av.z, scale, -(uv + wv.z)));
    r.w = ex2f(fmaf(av.w, scale, -(uv + wv.w)));
    *reinterpret_cast<float4*>(out + e) = r;
}

extern "C" void kernel_launch(void* const* d_in, const int* in_sizes, int n_in,
                              void* d_out, int out_size)
{
    const float* a   = (const float*)d_in[0];
    const float* tau = (const float*)d_in[1];
    float* out       = (float*)d_out;

    int b = in_sizes[0] / (NN * NN);          // 64 matrices

    for (int c0 = 0; c0 < b; c0 += CHUNK) {
        int nm = (b - c0 < CHUNK) ? (b - c0) : CHUNK;
        dim3 fg(nm * CPM),  fb(128);          // 64 CTAs per matrix
        dim3 vg(nm),        vb(256);
        dim3 og(nm * 1024), ob(256);

        // 6 passes. Pass p: reads B[(p+2)%3] (w), writes B[p%3] (new P sums),
        // zeroes B[(p+1)%3] (next pass's writer). B[0] starts zero.
        for (int p = 0; p < 6; ++p)
            fused_pass<<<fg, fb>>>(a, tau, p > 0, p == 5, c0,
                                   (p + 2) % 3, p % 3, (p + 1) % 3);
        // v5 from B[1] (sum P4), v6 from B[2] (sum P5); blend into g_w.
        vsum_final<<<vg, vb>>>(c0);
        // out = 2^(y - u6 - 0.5(v5+v6)), chunk still L2-hot.
        finalize_k<<<og, ob>>>(a, tau, out, c0);
    }
}